// round 9
// baseline (speedup 1.0000x reference)
#include <cuda_runtime.h>
#include <cuda_fp16.h>
#include <cstdint>

#define NB 16
#define CIN 256
#define LL 300
#define VV 25
#define PP 3
#define COUT 256
#define NCOL 120000
#define CPN 7500
#define KDIM 768
#define NKC 24            // K chunks of 32

#define BN 100            // 4 LN-frame groups per CTA
#define BSHB 120          // halves per B smem row (padded, LDSM bank-friendly)
#define ASTG 8192         // A halves per chunk
#define STAGE_B (ASTG * 2 + 32 * BSHB * 2)      // 24064 bytes per stage
#define NSTAGE 4
#define CS_STRIDE 261
#define GEMM_SMEM (BN * CS_STRIDE * 4)          // 104400 B (> 4*STAGE_B = 96256)

__device__ __half g_uh[(size_t)KDIM * NCOL];    // [k=(p,ci)][col] 184 MB
__device__ __half g_Afrag[COUT * KDIM];         // fp16 fragment-ordered Wall
__device__ float g_Aw[PP * VV * VV];
__device__ float g_bias2[COUT * VV];

__device__ __forceinline__ void cp16(uint32_t dst, const void* src) {
    asm volatile("cp.async.cg.shared.global [%0], [%1], 16;" :: "r"(dst), "l"(src));
}
__device__ __forceinline__ void cp8(uint32_t dst, const void* src) {
    asm volatile("cp.async.ca.shared.global [%0], [%1], 8;" :: "r"(dst), "l"(src));
}
__device__ __forceinline__ uint32_t smem_u32(const void* p) {
    uint32_t a;
    asm("{ .reg .u64 t; cvta.to.shared.u64 t, %1; cvt.u32.u64 %0, t; }" : "=r"(a) : "l"(p));
    return a;
}
__device__ __forceinline__ void mma_f16(float* d, uint32_t a0, uint32_t a1, uint32_t a2,
                                        uint32_t a3, uint32_t b0, uint32_t b1) {
    asm volatile(
        "mma.sync.aligned.m16n8k16.row.col.f32.f16.f16.f32 "
        "{%0,%1,%2,%3}, {%4,%5,%6,%7}, {%8,%9}, {%0,%1,%2,%3};"
        : "+f"(d[0]), "+f"(d[1]), "+f"(d[2]), "+f"(d[3])
        : "r"(a0), "r"(a1), "r"(a2), "r"(a3), "r"(b0), "r"(b1));
}
#define LDSM_X4_T(r0, r1, r2, r3, addr) \
    asm volatile("ldmatrix.sync.aligned.m8n8.x4.trans.shared.b16 {%0,%1,%2,%3}, [%4];" \
                 : "=r"(r0), "=r"(r1), "=r"(r2), "=r"(r3) : "r"(addr))
#define FMA_F32X2(acc, a, b) \
    asm("fma.rn.f32x2 %0, %1, %2, %0;" : "+l"(acc) : "l"(a), "l"(b))
#define PACK_F32X2(out, lo, hi) \
    asm("mov.b64 %0, {%1, %2};" : "=l"(out) : "f"(lo), "f"(hi))
#define UNPACK_F32X2(lo, hi, in) \
    asm("mov.b64 {%0, %1}, %2;" : "=f"(lo), "=f"(hi) : "l"(in))

// ---------------- prep: fp16 A fragments (M256 x 8-warp tiling), Aw, bias2 ---------
__global__ __launch_bounds__(256) void prep_kernel(const float* __restrict__ A,
                                                   const float* __restrict__ conv_w,
                                                   const float* __restrict__ conv_b,
                                                   const float* __restrict__ ei) {
    int e = blockIdx.x * 256 + threadIdx.x;
    if (e < COUT * KDIM) {
        int r = e / KDIM;
        int k = e - r * KDIM;
        int p = k >> 8, ci = k & 255;
        float w = conv_w[((p << 8) + r) * CIN + ci];
        int wm = r >> 5, fm = (r >> 4) & 1, rr = r & 15;
        int kchunk = k >> 5, k16 = (k >> 4) & 1, kkk = k & 15;
        int reg = (rr >> 3) | ((kkk >> 3) << 1);
        int lane = ((rr & 7) << 2) | ((kkk & 7) >> 1);
        int hl = kkk & 1;
        size_t off = ((((size_t)(kchunk * 8 + wm) * 2 + k16) * 2 + fm) * 256)
                     + lane * 8 + reg * 2 + hl;
        g_Afrag[off] = __float2half_rn(w);
    }
    if (e < PP * VV * VV) g_Aw[e] = A[e] * ei[e];
    if (e < COUT * VV) {
        int c = e / VV, w = e - (e / VV) * VV;
        float s = 0.f;
        for (int p = 0; p < PP; ++p) {
            float b = conv_b[(p << 8) + c];
            for (int v = 0; v < VV; ++v) {
                int a = (p * VV + v) * VV + w;
                s += b * A[a] * ei[a];
            }
        }
        g_bias2[e] = s;
    }
}

// ---------------- u kernel: window sum + graph agg, packed f32x2 math --------------
__global__ __launch_bounds__(256) void u_kernel(const float* __restrict__ x) {
    extern __shared__ __align__(16) float us[];
    float* xt = us;                           // 300 * 28 floats (16B-aligned rows)
    __half* ut = (__half*)(us + LL * 28);     // 7500 halves
    const int n = blockIdx.y;
    const int ci = blockIdx.x;
    const float* __restrict__ xr = x + ((size_t)(n * CIN + ci)) * CPN;
    const int t = threadIdx.x;

    // zero pad column v=25 (read by the last packed pair)
    for (int i = t; i < LL; i += 256) xt[i * 28 + 25] = 0.f;

    if (t < 250) {
        int v = t % 25;
        int mi = t / 25;
        int m0 = mi * 30;
        float s = 0.f;
        int lstart = m0 - 8; if (lstart < 0) lstart = 0;
        for (int l = lstart; l < m0; ++l) s += xr[l * VV + v];
        for (int m = m0; m < m0 + 30; ++m) {
            s += xr[m * VV + v];
            xt[m * 28 + v] = s;
            if (m >= 8) s -= xr[(m - 8) * VV + v];
        }
    }
    __syncthreads();

    const int w = t % 25;
    const int mg = t / 25;     // 0..9 (t<250)
    for (int p = 0; p < PP; ++p) {
        if (t < 250) {
            unsigned long long aw2[13];
#pragma unroll
            for (int j = 0; j < 12; ++j) {
                float a0 = g_Aw[(p * VV + 2 * j) * VV + w];
                float a1 = g_Aw[(p * VV + 2 * j + 1) * VV + w];
                PACK_F32X2(aw2[j], a0, a1);
            }
            {
                float a0 = g_Aw[(p * VV + 24) * VV + w];
                PACK_F32X2(aw2[12], a0, 0.f);
            }
            const int mend = mg * 30 + 30;
            for (int m = mg * 30; m < mend; ++m) {
                const ulonglong2* xv = (const ulonglong2*)(xt + m * 28);
                unsigned long long acc2 = 0ull;
#pragma unroll
                for (int q = 0; q < 6; ++q) {
                    ulonglong2 xx = xv[q];
                    FMA_F32X2(acc2, xx.x, aw2[2 * q]);
                    FMA_F32X2(acc2, xx.y, aw2[2 * q + 1]);
                }
                unsigned long long last = *(const unsigned long long*)(xt + m * 28 + 24);
                FMA_F32X2(acc2, last, aw2[12]);
                float lo, hi;
                UNPACK_F32X2(lo, hi, acc2);
                ut[m * VV + w] = __float2half_rn(lo + hi);
            }
        }
        __syncthreads();
        uint32_t* __restrict__ dst =
            (uint32_t*)(g_uh + (size_t)((p << 8) + ci) * NCOL + (size_t)n * CPN);
        const uint32_t* srcv = (const uint32_t*)ut;
        for (int i = t; i < CPN / 2; i += 256) dst[i] = srcv[i];
        __syncthreads();
    }
}

// ---------------- mega-GEMM: 512 threads, ldmatrix B frags, 4-stage pipe ----------
__global__ __launch_bounds__(512, 1) void gemm_kernel(const float* __restrict__ x,
                                                      const float* __restrict__ gamma,
                                                      const float* __restrict__ beta,
                                                      float* __restrict__ out) {
    extern __shared__ float dyns[];
    __half* sh = (__half*)dyns;
    __shared__ float red[16][4];
    __shared__ float smean[4], srstd[4];

    const int tid = threadIdx.x;
    const int warp = tid >> 5;
    const int lane = tid & 31;
    const int wm = warp >> 1;
    const int wn = warp & 1;
    const int grp = lane >> 2;
    const int tig = lane & 3;
    const int fnc = wn ? 6 : 7;
    const int bx = blockIdx.x;
    const int col0 = bx * BN;
    const int n = bx / 75;
    const int loc0 = (bx % 75) * BN;
    const int mf0 = (bx % 75) * 4;

    float acc[2][7][4];
#pragma unroll
    for (int i = 0; i < 2; ++i)
#pragma unroll
        for (int j = 0; j < 7; ++j)
#pragma unroll
            for (int r = 0; r < 4; ++r) acc[i][j][r] = 0.f;

    const uint32_t smem_base = smem_u32(dyns);

    for (int i = tid; i < NSTAGE * 32 * 10; i += 512) {
        int s = i / 320, rem = i - s * 320;
        int kk = rem / 10, j = rem - kk * 10;
        *(uint32_t*)((char*)sh + (size_t)s * STAGE_B + ASTG * 2
                     + (kk * BSHB + 100) * 2 + j * 4) = 0u;
    }

    auto load_chunk = [&](int s, int kc) {
        uint32_t As_b = smem_base + (uint32_t)s * STAGE_B;
        uint32_t Bs_b = As_b + ASTG * 2;
        const __half* Ag = g_Afrag + (size_t)kc * ASTG;
#pragma unroll
        for (int i = 0; i < 2; ++i) {
            int idx = i * 512 + tid;
            cp16(As_b + idx * 16, Ag + idx * 8);
        }
        {
            int i = tid;
            int kk = i / 25, cq = (i - kk * 25) * 4;
            cp8(Bs_b + (kk * BSHB + cq) * 2,
                g_uh + (size_t)(kc * 32 + kk) * NCOL + col0 + cq);
            i = tid + 512;
            if (i < 800) {
                kk = i / 25; cq = (i - kk * 25) * 4;
                cp8(Bs_b + (kk * BSHB + cq) * 2,
                    g_uh + (size_t)(kc * 32 + kk) * NCOL + col0 + cq);
            }
        }
        asm volatile("cp.async.commit_group;" ::: "memory");
    };

    load_chunk(0, 0);
    load_chunk(1, 1);
    load_chunk(2, 2);

    const int matid = lane >> 3;
    const int mrow = lane & 7;
    const int lds_row = (matid & 1) * 8 + mrow;
    const int lds_fn0 = wn * 7 + (matid >> 1);

    for (int kc = 0; kc < NKC; ++kc) {
        if (kc < NKC - 2)       asm volatile("cp.async.wait_group 2;" ::: "memory");
        else if (kc == NKC - 2) asm volatile("cp.async.wait_group 1;" ::: "memory");
        else                    asm volatile("cp.async.wait_group 0;" ::: "memory");
        __syncthreads();

        if (kc + 3 < NKC) load_chunk((kc + 3) & 3, kc + 3);

        const int s = kc & 3;
        const __half* As = sh + (size_t)s * STAGE_B / 2;
        const uint32_t Bs_b = smem_base + (uint32_t)s * STAGE_B + ASTG * 2;

#pragma unroll
        for (int k16 = 0; k16 < 2; ++k16) {
            uint4 a0 = *(const uint4*)(As + (((wm * 2 + k16) * 2 + 0) << 8) + lane * 8);
            uint4 a1 = *(const uint4*)(As + (((wm * 2 + k16) * 2 + 1) << 8) + lane * 8);
            uint32_t bfr[16];
            uint32_t baddr = Bs_b + ((k16 * 16 + lds_row) * BSHB + lds_fn0 * 8) * 2;
#pragma unroll
            for (int j = 0; j < 4; ++j) {
                if (wn == 0 || j < 3)
                    LDSM_X4_T(bfr[4 * j], bfr[4 * j + 1], bfr[4 * j + 2], bfr[4 * j + 3],
                              baddr + j * 32);
            }
#pragma unroll
            for (int f = 0; f < 7; ++f) {
                if (f < fnc) {
                    mma_f16(acc[0][f], a0.x, a0.y, a0.z, a0.w, bfr[2 * f], bfr[2 * f + 1]);
                    mma_f16(acc[1][f], a1.x, a1.y, a1.z, a1.w, bfr[2 * f], bfr[2 * f + 1]);
                }
            }
        }
        // no trailing barrier: next iteration's top barrier orders stage reuse
    }
    __syncthreads();

    // ---------- epilogue: stage z + bias into Cs[e][c] ----------
    float* Cs = dyns;
#pragma unroll
    for (int fm = 0; fm < 2; ++fm)
#pragma unroll
        for (int f = 0; f < 7; ++f)
#pragma unroll
            for (int r = 0; r < 4; ++r) {
                int nn = wn * 56 + f * 8 + 2 * tig + (r & 1);
                if (f < fnc && nn < BN) {
                    int c = wm * 32 + fm * 16 + grp + ((r & 2) ? 8 : 0);
                    int g = nn / 25;
                    int w = nn - g * 25;
                    int mf = mf0 + g;
                    float cnt = (float)((mf + 1 < 9) ? (mf + 1) : 9);
                    Cs[nn * CS_STRIDE + c] = acc[fm][f][r] + cnt * g_bias2[c * VV + w];
                }
            }
    __syncthreads();

    // ---------- LN stats ----------
    {
        const int half = tid >> 8;
        const int c = tid & 255;
        float s0 = 0.f, q0 = 0.f, s1 = 0.f, q1 = 0.f;
        const float* c0p = Cs + (half * 2 + 0) * 25 * CS_STRIDE + c;
        const float* c1p = Cs + (half * 2 + 1) * 25 * CS_STRIDE + c;
#pragma unroll
        for (int w = 0; w < 25; ++w) {
            float v0 = c0p[w * CS_STRIDE];
            float v1 = c1p[w * CS_STRIDE];
            s0 += v0; q0 += v0 * v0;
            s1 += v1; q1 += v1 * v1;
        }
#pragma unroll
        for (int off = 16; off > 0; off >>= 1) {
            s0 += __shfl_down_sync(0xffffffffu, s0, off);
            q0 += __shfl_down_sync(0xffffffffu, q0, off);
            s1 += __shfl_down_sync(0xffffffffu, s1, off);
            q1 += __shfl_down_sync(0xffffffffu, q1, off);
        }
        if (lane == 0) {
            red[warp][0] = s0; red[warp][1] = q0;
            red[warp][2] = s1; red[warp][3] = q1;
        }
    }
    __syncthreads();
    if (tid < 4) {
        int hw = (tid >> 1) * 8;
        int sel = (tid & 1) * 2;
        float s = 0.f, q = 0.f;
#pragma unroll
        for (int w = 0; w < 8; ++w) { s += red[hw + w][sel]; q += red[hw + w][sel + 1]; }
        const float inv = 1.f / 6400.f;
        float mean = s * inv;
        float var = q * inv - mean * mean;
        smean[tid] = mean;
        srstd[tid] = rsqrtf(var + 1e-5f);
    }
    __syncthreads();

    // ---------- apply LN + gamma/beta + relu in Cs ----------
    {
        const int half = tid >> 8;
        const int c = tid & 255;
        const float* gm = gamma + c * VV;
        const float* bt = beta + c * VV;
#pragma unroll
        for (int gg = 0; gg < 2; ++gg) {
            int g = half * 2 + gg;
            float mean = smean[g], rstd = srstd[g];
            float* cp = Cs + g * 25 * CS_STRIDE + c;
            for (int w = 0; w < 25; ++w) {
                float z = cp[w * CS_STRIDE];
                float yv = (z - mean) * rstd * gm[w] + bt[w];
                cp[w * CS_STRIDE] = fmaxf(yv, 0.f);
            }
        }
    }
    __syncthreads();

    // ---------- residual + final relu, coalesced float4 ----------
    for (int i = 0; i < 13; ++i) {
        int idx = i * 512 + tid;
        if (idx < 6400) {
            int c = idx / 25;
            int j = idx - c * 25;
            size_t base = ((size_t)(n * CIN + c)) * CPN + loc0 + j * 4;
            float4 xv = *(const float4*)(x + base);
            int e = j * 4;
            float4 yv;
            yv.x = fmaxf(Cs[(e + 0) * CS_STRIDE + c] + xv.x, 0.f);
            yv.y = fmaxf(Cs[(e + 1) * CS_STRIDE + c] + xv.y, 0.f);
            yv.z = fmaxf(Cs[(e + 2) * CS_STRIDE + c] + xv.z, 0.f);
            yv.w = fmaxf(Cs[(e + 3) * CS_STRIDE + c] + xv.w, 0.f);
            *(float4*)(out + base) = yv;
        }
    }
}

// ---------------------------------------------------------------------------
extern "C" void kernel_launch(void* const* d_in, const int* in_sizes, int n_in,
                              void* d_out, int out_size) {
    const float* x      = (const float*)d_in[0];
    const float* A      = (const float*)d_in[1];
    const float* conv_w = (const float*)d_in[2];
    const float* conv_b = (const float*)d_in[3];
    const float* gamma  = (const float*)d_in[4];
    const float* beta   = (const float*)d_in[5];
    const float* ei     = (const float*)d_in[6];
    float* out = (float*)d_out;

    const int USMEM = LL * 28 * 4 + CPN * 2;   // 48600 bytes
    cudaFuncSetAttribute(gemm_kernel, cudaFuncAttributeMaxDynamicSharedMemorySize, GEMM_SMEM);
    cudaFuncSetAttribute(u_kernel, cudaFuncAttributeMaxDynamicSharedMemorySize, USMEM);

    prep_kernel<<<(COUT * KDIM + 255) / 256, 256>>>(A, conv_w, conv_b, ei);

    dim3 gu(CIN, NB);
    u_kernel<<<gu, 256, USMEM>>>(x);

    gemm_kernel<<<NCOL / BN, 512, GEMM_SMEM>>>(x, gamma, beta, out);
}

// round 10
// speedup vs baseline: 1.1142x; 1.1142x over previous
#include <cuda_runtime.h>
#include <cuda_fp16.h>
#include <cstdint>

#define NB 16
#define CIN 256
#define LL 300
#define VV 25
#define PP 3
#define COUT 256
#define NCOL 120000
#define CPN 7500
#define KDIM 768
#define NKC 24            // K chunks of 32

#define BN 100            // 4 LN-frame groups per CTA
#define BSHB 120          // halves per B smem row (padded, LDSM bank-friendly)
#define ASTG 8192         // A halves per chunk
#define STAGE_B (ASTG * 2 + 32 * BSHB * 2)      // 24064 bytes per stage
#define NSTAGE 4
#define CS_STRIDE 261
#define GEMM_SMEM (BN * CS_STRIDE * 4)          // 104400 B (> 4*STAGE_B = 96256)

__device__ __half g_uh[(size_t)KDIM * NCOL];    // [k=(p,ci)][col] 184 MB
__device__ __half g_Afrag[COUT * KDIM];         // fp16 fragment-ordered Wall
__device__ float g_Aw[PP * VV * VV];
__device__ float g_bias2[COUT * VV];

__device__ __forceinline__ void cp16(uint32_t dst, const void* src) {
    asm volatile("cp.async.cg.shared.global [%0], [%1], 16;" :: "r"(dst), "l"(src));
}
__device__ __forceinline__ void cp8(uint32_t dst, const void* src) {
    asm volatile("cp.async.ca.shared.global [%0], [%1], 8;" :: "r"(dst), "l"(src));
}
__device__ __forceinline__ uint32_t smem_u32(const void* p) {
    uint32_t a;
    asm("{ .reg .u64 t; cvta.to.shared.u64 t, %1; cvt.u32.u64 %0, t; }" : "=r"(a) : "l"(p));
    return a;
}
__device__ __forceinline__ void mma_f16(float* d, uint32_t a0, uint32_t a1, uint32_t a2,
                                        uint32_t a3, uint32_t b0, uint32_t b1) {
    asm volatile(
        "mma.sync.aligned.m16n8k16.row.col.f32.f16.f16.f32 "
        "{%0,%1,%2,%3}, {%4,%5,%6,%7}, {%8,%9}, {%0,%1,%2,%3};"
        : "+f"(d[0]), "+f"(d[1]), "+f"(d[2]), "+f"(d[3])
        : "r"(a0), "r"(a1), "r"(a2), "r"(a3), "r"(b0), "r"(b1));
}
#define LDSM_X4_T(r0, r1, r2, r3, addr) \
    asm volatile("ldmatrix.sync.aligned.m8n8.x4.trans.shared.b16 {%0,%1,%2,%3}, [%4];" \
                 : "=r"(r0), "=r"(r1), "=r"(r2), "=r"(r3) : "r"(addr))

// ---------------- prep: fp16 A fragments (M256 x 8-warp tiling), Aw, bias2 ---------
__global__ __launch_bounds__(256) void prep_kernel(const float* __restrict__ A,
                                                   const float* __restrict__ conv_w,
                                                   const float* __restrict__ conv_b,
                                                   const float* __restrict__ ei) {
    int e = blockIdx.x * 256 + threadIdx.x;
    if (e < COUT * KDIM) {
        int r = e / KDIM;
        int k = e - r * KDIM;
        int p = k >> 8, ci = k & 255;
        float w = conv_w[((p << 8) + r) * CIN + ci];
        int wm = r >> 5, fm = (r >> 4) & 1, rr = r & 15;
        int kchunk = k >> 5, k16 = (k >> 4) & 1, kkk = k & 15;
        int reg = (rr >> 3) | ((kkk >> 3) << 1);
        int lane = ((rr & 7) << 2) | ((kkk & 7) >> 1);
        int hl = kkk & 1;
        size_t off = ((((size_t)(kchunk * 8 + wm) * 2 + k16) * 2 + fm) * 256)
                     + lane * 8 + reg * 2 + hl;
        g_Afrag[off] = __float2half_rn(w);
    }
    if (e < PP * VV * VV) g_Aw[e] = A[e] * ei[e];
    if (e < COUT * VV) {
        int c = e / VV, w = e - (e / VV) * VV;
        float s = 0.f;
        for (int p = 0; p < PP; ++p) {
            float b = conv_b[(p << 8) + c];
            for (int v = 0; v < VV; ++v) {
                int a = (p * VV + v) * VV + w;
                s += b * A[a] * ei[a];
            }
        }
        g_bias2[e] = s;
    }
}

// ---------------- u kernel: window sum + graph agg (R8 verified) -------------------
__global__ __launch_bounds__(256) void u_kernel(const float* __restrict__ x) {
    extern __shared__ __align__(16) float us[];
    float* xt = us;                           // 300 * 28 floats
    __half* ut = (__half*)(us + LL * 28);     // 7500 halves
    const int n = blockIdx.y;
    const int ci = blockIdx.x;
    const float* __restrict__ xr = x + ((size_t)(n * CIN + ci)) * CPN;
    const int t = threadIdx.x;

    if (t < 250) {
        int v = t % 25;
        int mi = t / 25;
        int m0 = mi * 30;
        float s = 0.f;
        int lstart = m0 - 8; if (lstart < 0) lstart = 0;
        for (int l = lstart; l < m0; ++l) s += xr[l * VV + v];
        for (int m = m0; m < m0 + 30; ++m) {
            s += xr[m * VV + v];
            xt[m * 28 + v] = s;
            if (m >= 8) s -= xr[(m - 8) * VV + v];
        }
    }
    __syncthreads();

    const int w = t & 31;
    const int mg = t >> 5;
    float aw[25];
    for (int p = 0; p < PP; ++p) {
        if (w < 25) {
#pragma unroll
            for (int v = 0; v < 25; ++v) aw[v] = g_Aw[(p * VV + v) * VV + w];
            for (int m = mg; m < LL; m += 8) {
                const float4* xv4 = (const float4*)(xt + m * 28);
                float acc = 0.f;
#pragma unroll
                for (int q = 0; q < 6; ++q) {
                    float4 xv = xv4[q];
                    acc += xv.x * aw[4 * q + 0];
                    acc += xv.y * aw[4 * q + 1];
                    acc += xv.z * aw[4 * q + 2];
                    acc += xv.w * aw[4 * q + 3];
                }
                acc += xt[m * 28 + 24] * aw[24];
                ut[m * VV + w] = __float2half_rn(acc);
            }
        }
        __syncthreads();
        uint32_t* __restrict__ dst =
            (uint32_t*)(g_uh + (size_t)((p << 8) + ci) * NCOL + (size_t)n * CPN);
        const uint32_t* srcv = (const uint32_t*)ut;
        for (int i = t; i < CPN / 2; i += 256) dst[i] = srcv[i];
        __syncthreads();
    }
}

// ---------------- mega-GEMM: 512 threads, ldmatrix B frags, 2 chunks per sync -----
__global__ __launch_bounds__(512, 1) void gemm_kernel(const float* __restrict__ x,
                                                      const float* __restrict__ gamma,
                                                      const float* __restrict__ beta,
                                                      float* __restrict__ out) {
    extern __shared__ float dyns[];
    __half* sh = (__half*)dyns;
    __shared__ float red[16][4];
    __shared__ float smean[4], srstd[4];

    const int tid = threadIdx.x;
    const int warp = tid >> 5;
    const int lane = tid & 31;
    const int wm = warp >> 1;
    const int wn = warp & 1;
    const int grp = lane >> 2;
    const int tig = lane & 3;
    const int fnc = wn ? 6 : 7;
    const int bx = blockIdx.x;
    const int col0 = bx * BN;
    const int n = bx / 75;
    const int loc0 = (bx % 75) * BN;
    const int mf0 = (bx % 75) * 4;

    float acc[2][7][4];
#pragma unroll
    for (int i = 0; i < 2; ++i)
#pragma unroll
        for (int j = 0; j < 7; ++j)
#pragma unroll
            for (int r = 0; r < 4; ++r) acc[i][j][r] = 0.f;

    const uint32_t smem_base = smem_u32(dyns);

    // zero B pad columns (halves 100..119) in all stages; never touched by cp.async
    for (int i = tid; i < NSTAGE * 32 * 10; i += 512) {
        int s = i / 320, rem = i - s * 320;
        int kk = rem / 10, j = rem - kk * 10;
        *(uint32_t*)((char*)sh + (size_t)s * STAGE_B + ASTG * 2
                     + (kk * BSHB + 100) * 2 + j * 4) = 0u;
    }

    auto load_chunk = [&](int s, int kc) {
        uint32_t As_b = smem_base + (uint32_t)s * STAGE_B;
        uint32_t Bs_b = As_b + ASTG * 2;
        const __half* Ag = g_Afrag + (size_t)kc * ASTG;
#pragma unroll
        for (int i = 0; i < 2; ++i) {
            int idx = i * 512 + tid;
            cp16(As_b + idx * 16, Ag + idx * 8);
        }
        {
            int i = tid;
            int kk = i / 25, cq = (i - kk * 25) * 4;
            cp8(Bs_b + (kk * BSHB + cq) * 2,
                g_uh + (size_t)(kc * 32 + kk) * NCOL + col0 + cq);
            i = tid + 512;
            if (i < 800) {
                kk = i / 25; cq = (i - kk * 25) * 4;
                cp8(Bs_b + (kk * BSHB + cq) * 2,
                    g_uh + (size_t)(kc * 32 + kk) * NCOL + col0 + cq);
            }
        }
        asm volatile("cp.async.commit_group;" ::: "memory");
    };

    // prologue: fill all 4 stages (chunks 0..3)
    load_chunk(0, 0);
    load_chunk(1, 1);
    load_chunk(2, 2);
    load_chunk(3, 3);

    const int matid = lane >> 3;
    const int mrow = lane & 7;
    const int lds_row = (matid & 1) * 8 + mrow;
    const int lds_fn0 = wn * 7 + (matid >> 1);

    for (int it = 0; it < NKC / 2; ++it) {
        if (it < NKC / 2 - 1) asm volatile("cp.async.wait_group 2;" ::: "memory");
        else                  asm volatile("cp.async.wait_group 0;" ::: "memory");
        __syncthreads();

#pragma unroll
        for (int h = 0; h < 2; ++h) {
            const int kc = 2 * it + h;
            const int s = kc & 3;
            const __half* As = sh + (size_t)s * STAGE_B / 2;
            const uint32_t Bs_b = smem_base + (uint32_t)s * STAGE_B + ASTG * 2;

#pragma unroll
            for (int k16 = 0; k16 < 2; ++k16) {
                uint4 a0 = *(const uint4*)(As + (((wm * 2 + k16) * 2 + 0) << 8) + lane * 8);
                uint4 a1 = *(const uint4*)(As + (((wm * 2 + k16) * 2 + 1) << 8) + lane * 8);
                uint32_t bfr[16];
                uint32_t baddr = Bs_b + ((k16 * 16 + lds_row) * BSHB + lds_fn0 * 8) * 2;
#pragma unroll
                for (int j = 0; j < 4; ++j) {
                    if (wn == 0 || j < 3)
                        LDSM_X4_T(bfr[4 * j], bfr[4 * j + 1], bfr[4 * j + 2], bfr[4 * j + 3],
                                  baddr + j * 32);
                }
#pragma unroll
                for (int f = 0; f < 7; ++f) {
                    if (f < fnc) {
                        mma_f16(acc[0][f], a0.x, a0.y, a0.z, a0.w, bfr[2 * f], bfr[2 * f + 1]);
                        mma_f16(acc[1][f], a1.x, a1.y, a1.z, a1.w, bfr[2 * f], bfr[2 * f + 1]);
                    }
                }
            }
        }
        __syncthreads();
        if (2 * it + 5 < NKC) {
            load_chunk((2 * it + 4) & 3, 2 * it + 4);
            load_chunk((2 * it + 5) & 3, 2 * it + 5);
        }
    }
    __syncthreads();

    // ---------- epilogue: stage z + bias into Cs[e][c] ----------
    float* Cs = dyns;
#pragma unroll
    for (int fm = 0; fm < 2; ++fm)
#pragma unroll
        for (int f = 0; f < 7; ++f)
#pragma unroll
            for (int r = 0; r < 4; ++r) {
                int nn = wn * 56 + f * 8 + 2 * tig + (r & 1);
                if (f < fnc && nn < BN) {
                    int c = wm * 32 + fm * 16 + grp + ((r & 2) ? 8 : 0);
                    int g = nn / 25;
                    int w = nn - g * 25;
                    int mf = mf0 + g;
                    float cnt = (float)((mf + 1 < 9) ? (mf + 1) : 9);
                    Cs[nn * CS_STRIDE + c] = acc[fm][f][r] + cnt * g_bias2[c * VV + w];
                }
            }
    __syncthreads();

    // ---------- LN stats ----------
    {
        const int half = tid >> 8;
        const int c = tid & 255;
        float s0 = 0.f, q0 = 0.f, s1 = 0.f, q1 = 0.f;
        const float* c0p = Cs + (half * 2 + 0) * 25 * CS_STRIDE + c;
        const float* c1p = Cs + (half * 2 + 1) * 25 * CS_STRIDE + c;
#pragma unroll
        for (int w = 0; w < 25; ++w) {
            float v0 = c0p[w * CS_STRIDE];
            float v1 = c1p[w * CS_STRIDE];
            s0 += v0; q0 += v0 * v0;
            s1 += v1; q1 += v1 * v1;
        }
#pragma unroll
        for (int off = 16; off > 0; off >>= 1) {
            s0 += __shfl_down_sync(0xffffffffu, s0, off);
            q0 += __shfl_down_sync(0xffffffffu, q0, off);
            s1 += __shfl_down_sync(0xffffffffu, s1, off);
            q1 += __shfl_down_sync(0xffffffffu, q1, off);
        }
        if (lane == 0) {
            red[warp][0] = s0; red[warp][1] = q0;
            red[warp][2] = s1; red[warp][3] = q1;
        }
    }
    __syncthreads();
    if (tid < 4) {
        int hw = (tid >> 1) * 8;
        int sel = (tid & 1) * 2;
        float s = 0.f, q = 0.f;
#pragma unroll
        for (int w = 0; w < 8; ++w) { s += red[hw + w][sel]; q += red[hw + w][sel + 1]; }
        const float inv = 1.f / 6400.f;
        float mean = s * inv;
        float var = q * inv - mean * mean;
        smean[tid] = mean;
        srstd[tid] = rsqrtf(var + 1e-5f);
    }
    __syncthreads();

    // ---------- apply LN + gamma/beta + relu in Cs ----------
    {
        const int half = tid >> 8;
        const int c = tid & 255;
        const float* gm = gamma + c * VV;
        const float* bt = beta + c * VV;
#pragma unroll
        for (int gg = 0; gg < 2; ++gg) {
            int g = half * 2 + gg;
            float mean = smean[g], rstd = srstd[g];
            float* cp = Cs + g * 25 * CS_STRIDE + c;
            for (int w = 0; w < 25; ++w) {
                float z = cp[w * CS_STRIDE];
                float yv = (z - mean) * rstd * gm[w] + bt[w];
                cp[w * CS_STRIDE] = fmaxf(yv, 0.f);
            }
        }
    }
    __syncthreads();

    // ---------- residual + final relu, coalesced float4 ----------
    for (int i = 0; i < 13; ++i) {
        int idx = i * 512 + tid;
        if (idx < 6400) {
            int c = idx / 25;
            int j = idx - c * 25;
            size_t base = ((size_t)(n * CIN + c)) * CPN + loc0 + j * 4;
            float4 xv = *(const float4*)(x + base);
            int e = j * 4;
            float4 yv;
            yv.x = fmaxf(Cs[(e + 0) * CS_STRIDE + c] + xv.x, 0.f);
            yv.y = fmaxf(Cs[(e + 1) * CS_STRIDE + c] + xv.y, 0.f);
            yv.z = fmaxf(Cs[(e + 2) * CS_STRIDE + c] + xv.z, 0.f);
            yv.w = fmaxf(Cs[(e + 3) * CS_STRIDE + c] + xv.w, 0.f);
            *(float4*)(out + base) = yv;
        }
    }
}

// ---------------------------------------------------------------------------
extern "C" void kernel_launch(void* const* d_in, const int* in_sizes, int n_in,
                              void* d_out, int out_size) {
    const float* x      = (const float*)d_in[0];
    const float* A      = (const float*)d_in[1];
    const float* conv_w = (const float*)d_in[2];
    const float* conv_b = (const float*)d_in[3];
    const float* gamma  = (const float*)d_in[4];
    const float* beta   = (const float*)d_in[5];
    const float* ei     = (const float*)d_in[6];
    float* out = (float*)d_out;

    const int USMEM = LL * 28 * 4 + CPN * 2;   // 48600 bytes
    cudaFuncSetAttribute(gemm_kernel, cudaFuncAttributeMaxDynamicSharedMemorySize, GEMM_SMEM);
    cudaFuncSetAttribute(u_kernel, cudaFuncAttributeMaxDynamicSharedMemorySize, USMEM);

    prep_kernel<<<(COUT * KDIM + 255) / 256, 256>>>(A, conv_w, conv_b, ei);

    dim3 gu(CIN, NB);
    u_kernel<<<gu, 256, USMEM>>>(x);

    gemm_kernel<<<NCOL / BN, 512, GEMM_SMEM>>>(x, gamma, beta, out);
}

// round 11
// speedup vs baseline: 1.5176x; 1.3620x over previous
#include <cuda_runtime.h>
#include <cuda_fp16.h>
#include <cstdint>

#define NB 16
#define CIN 256
#define LL 300
#define VV 25
#define PP 3
#define COUT 256
#define NCOL 120000
#define CPN 7500
#define KDIM 768
#define NKC 24            // K chunks of 32

#define BN 100            // 4 LN-frame groups per CTA
#define BSHB 120          // halves per B smem row (padded, LDSM bank-friendly)
#define ASTG 8192         // A halves per chunk
#define STAGE_B (ASTG * 2 + 32 * BSHB * 2)      // 24064 bytes per stage
#define NSTAGE 4
#define CS_STRIDE 261
#define GEMM_SMEM (BN * CS_STRIDE * 4)          // 104400 B (> 4*STAGE_B = 96256)

// u2 kernel smem: XT[320][40] halves (25600 B) + union{ xraw 30000 B, ust[320][80] halves 51200 B }
#define U2_SMEM (25600 + 51200)

__device__ __half g_uh[(size_t)KDIM * NCOL];    // [k=(p,ci)][col] 184 MB
__device__ __half g_Afrag[COUT * KDIM];         // fp16 fragment-ordered Wall
__device__ uint32_t g_AwFrag[10 * 2 * 32 * 2];  // B-fragment-packed Aw [nt][k16][lane][j]
__device__ float g_bias2[COUT * VV];

__device__ __forceinline__ void cp16(uint32_t dst, const void* src) {
    asm volatile("cp.async.cg.shared.global [%0], [%1], 16;" :: "r"(dst), "l"(src));
}
__device__ __forceinline__ void cp8(uint32_t dst, const void* src) {
    asm volatile("cp.async.ca.shared.global [%0], [%1], 8;" :: "r"(dst), "l"(src));
}
__device__ __forceinline__ uint32_t smem_u32(const void* p) {
    uint32_t a;
    asm("{ .reg .u64 t; cvta.to.shared.u64 t, %1; cvt.u32.u64 %0, t; }" : "=r"(a) : "l"(p));
    return a;
}
__device__ __forceinline__ void mma_f16(float* d, uint32_t a0, uint32_t a1, uint32_t a2,
                                        uint32_t a3, uint32_t b0, uint32_t b1) {
    asm volatile(
        "mma.sync.aligned.m16n8k16.row.col.f32.f16.f16.f32 "
        "{%0,%1,%2,%3}, {%4,%5,%6,%7}, {%8,%9}, {%0,%1,%2,%3};"
        : "+f"(d[0]), "+f"(d[1]), "+f"(d[2]), "+f"(d[3])
        : "r"(a0), "r"(a1), "r"(a2), "r"(a3), "r"(b0), "r"(b1));
}
#define LDSM_X4_T(r0, r1, r2, r3, addr) \
    asm volatile("ldmatrix.sync.aligned.m8n8.x4.trans.shared.b16 {%0,%1,%2,%3}, [%4];" \
                 : "=r"(r0), "=r"(r1), "=r"(r2), "=r"(r3) : "r"(addr))
#define LDSM_X4(r0, r1, r2, r3, addr) \
    asm volatile("ldmatrix.sync.aligned.m8n8.x4.shared.b16 {%0,%1,%2,%3}, [%4];" \
                 : "=r"(r0), "=r"(r1), "=r"(r2), "=r"(r3) : "r"(addr))

// ---------------- prep: fp16 A fragments, AwFrag (B-fragment Aw), bias2 ------------
__global__ __launch_bounds__(256) void prep_kernel(const float* __restrict__ A,
                                                   const float* __restrict__ conv_w,
                                                   const float* __restrict__ conv_b,
                                                   const float* __restrict__ ei) {
    int e = blockIdx.x * 256 + threadIdx.x;
    if (e < COUT * KDIM) {
        int r = e / KDIM;
        int k = e - r * KDIM;
        int p = k >> 8, ci = k & 255;
        float w = conv_w[((p << 8) + r) * CIN + ci];
        int wm = r >> 5, fm = (r >> 4) & 1, rr = r & 15;
        int kchunk = k >> 5, k16 = (k >> 4) & 1, kkk = k & 15;
        int reg = (rr >> 3) | ((kkk >> 3) << 1);
        int lane = ((rr & 7) << 2) | ((kkk & 7) >> 1);
        int hl = kkk & 1;
        size_t off = ((((size_t)(kchunk * 8 + wm) * 2 + k16) * 2 + fm) * 256)
                     + lane * 8 + reg * 2 + hl;
        g_Afrag[off] = __float2half_rn(w);
    }
    if (e < 1280) {
        // AwFrag: e = ((nt*2 + k16)*32 + lane)*2 + j
        int j = e & 1;
        int lane = (e >> 1) & 31;
        int k16 = (e >> 6) & 1;
        int nt = e >> 7;               // 0..9
        int grp = lane >> 2, tig = lane & 3;
        int nn = nt * 8 + grp;
        int klo = k16 * 16 + j * 8 + 2 * tig;
        float v0 = 0.f, v1 = 0.f;
        if (nn < 75) {
            int p = nn / 25, w = nn - (nn / 25) * 25;
            if (klo < 25) {
                int a = (p * VV + klo) * VV + w;
                v0 = A[a] * ei[a];
            }
            if (klo + 1 < 25) {
                int a = (p * VV + klo + 1) * VV + w;
                v1 = A[a] * ei[a];
            }
        }
        __half2 h2 = __floats2half2_rn(v0, v1);
        g_AwFrag[e] = *(uint32_t*)&h2;
    }
    if (e < COUT * VV) {
        int c = e / VV, w = e - (e / VV) * VV;
        float s = 0.f;
        for (int p = 0; p < PP; ++p) {
            float b = conv_b[(p << 8) + c];
            for (int v = 0; v < VV; ++v) {
                int a = (p * VV + v) * VV + w;
                s += b * A[a] * ei[a];
            }
        }
        g_bias2[e] = s;
    }
}

// ---------------- u kernel (tensor-core): U[300x75] = XT[300x25] @ Aw[25x75] -------
__global__ __launch_bounds__(256) void u_kernel(const float* __restrict__ x) {
    extern __shared__ __align__(16) char us2[];
    __half* XT = (__half*)us2;                    // [320][40] halves
    float* xraw = (float*)(us2 + 25600);          // 7500 floats (aliases ust)
    __half* ust = (__half*)(us2 + 25600);         // [320][80] halves

    const int n = blockIdx.y;
    const int ci = blockIdx.x;
    const int t = threadIdx.x;
    const int warp = t >> 5;
    const int lane = t & 31;
    const int grp = lane >> 2;
    const int tig = lane & 3;

    // load x row (contiguous 7500 floats), zero XT
    {
        const float4* xg = (const float4*)(x + (size_t)(n * CIN + ci) * CPN);
        float4* xs4 = (float4*)xraw;
        for (int i = t; i < 1875; i += 256) xs4[i] = xg[i];
        uint32_t* xtz = (uint32_t*)XT;
        for (int i = t; i < 6400; i += 256) xtz[i] = 0u;
    }
    __syncthreads();

    // window sums -> XT fp16
    if (t < 250) {
        int v = t % 25, mi = t / 25, m0 = mi * 30;
        float s = 0.f;
        int lst = m0 - 8; if (lst < 0) lst = 0;
        for (int l = lst; l < m0; ++l) s += xraw[l * 25 + v];
        for (int m = m0; m < m0 + 30; ++m) {
            s += xraw[m * 25 + v];
            XT[m * 40 + v] = __float2half_rn(s);
            if (m >= 8) s -= xraw[(m - 8) * 25 + v];
        }
    }
    __syncthreads();

    // load constant B fragments (Aw), 40 regs per thread
    uint32_t b[10][2][2];
#pragma unroll
    for (int nt = 0; nt < 10; ++nt)
#pragma unroll
        for (int k16 = 0; k16 < 2; ++k16)
#pragma unroll
            for (int j = 0; j < 2; ++j)
                b[nt][k16][j] = g_AwFrag[((nt * 2 + k16) * 32 + lane) * 2 + j];

    const uint32_t xt_base = smem_u32(XT);
    const int lrow = lane & 15;
    const int lcol = lane >> 4;

    for (int mt = warp; mt < 19; mt += 8) {
        float acc[10][4];
#pragma unroll
        for (int nt = 0; nt < 10; ++nt)
#pragma unroll
            for (int r = 0; r < 4; ++r) acc[nt][r] = 0.f;

#pragma unroll
        for (int k16 = 0; k16 < 2; ++k16) {
            uint32_t addr = xt_base + ((mt * 16 + lrow) * 40 + k16 * 16 + lcol * 8) * 2;
            uint32_t a0, a1, a2, a3;
            LDSM_X4(a0, a1, a2, a3, addr);
#pragma unroll
            for (int nt = 0; nt < 10; ++nt)
                mma_f16(acc[nt], a0, a1, a2, a3, b[nt][k16][0], b[nt][k16][1]);
        }

        // store to ust[m][80] as half2 pairs
#pragma unroll
        for (int nt = 0; nt < 10; ++nt) {
            __half2 lo = __floats2half2_rn(acc[nt][0], acc[nt][1]);
            __half2 hi = __floats2half2_rn(acc[nt][2], acc[nt][3]);
            int colb = nt * 8 + 2 * tig;
            *(uint32_t*)&ust[(mt * 16 + grp) * 80 + colb] = *(uint32_t*)&lo;
            *(uint32_t*)&ust[(mt * 16 + grp + 8) * 80 + colb] = *(uint32_t*)&hi;
        }
    }
    __syncthreads();

    // copy out: g_uh[(p*256+ci)][n*7500 + m*25 + w] = ust[m][p*25+w]
#pragma unroll
    for (int p = 0; p < 3; ++p) {
        __half* __restrict__ dst = g_uh + (size_t)((p << 8) + ci) * NCOL + (size_t)n * CPN;
        for (int f = t; f < CPN; f += 256) {
            int m = f / 25, w = f - m * 25;
            dst[f] = ust[m * 80 + p * 25 + w];
        }
    }
}

// ---------------- mega-GEMM: 512 threads, ldmatrix B frags, 2 chunks per sync -----
__global__ __launch_bounds__(512, 1) void gemm_kernel(const float* __restrict__ x,
                                                      const float* __restrict__ gamma,
                                                      const float* __restrict__ beta,
                                                      float* __restrict__ out) {
    extern __shared__ float dyns[];
    __half* sh = (__half*)dyns;
    __shared__ float red[16][4];
    __shared__ float smean[4], srstd[4];

    const int tid = threadIdx.x;
    const int warp = tid >> 5;
    const int lane = tid & 31;
    const int wm = warp >> 1;
    const int wn = warp & 1;
    const int grp = lane >> 2;
    const int tig = lane & 3;
    const int fnc = wn ? 6 : 7;
    const int bx = blockIdx.x;
    const int col0 = bx * BN;
    const int n = bx / 75;
    const int loc0 = (bx % 75) * BN;
    const int mf0 = (bx % 75) * 4;

    float acc[2][7][4];
#pragma unroll
    for (int i = 0; i < 2; ++i)
#pragma unroll
        for (int j = 0; j < 7; ++j)
#pragma unroll
            for (int r = 0; r < 4; ++r) acc[i][j][r] = 0.f;

    const uint32_t smem_base = smem_u32(dyns);

    // zero B pad columns (halves 100..119) in all stages; never touched by cp.async
    for (int i = tid; i < NSTAGE * 32 * 10; i += 512) {
        int s = i / 320, rem = i - s * 320;
        int kk = rem / 10, j = rem - kk * 10;
        *(uint32_t*)((char*)sh + (size_t)s * STAGE_B + ASTG * 2
                     + (kk * BSHB + 100) * 2 + j * 4) = 0u;
    }

    auto load_chunk = [&](int s, int kc) {
        uint32_t As_b = smem_base + (uint32_t)s * STAGE_B;
        uint32_t Bs_b = As_b + ASTG * 2;
        const __half* Ag = g_Afrag + (size_t)kc * ASTG;
#pragma unroll
        for (int i = 0; i < 2; ++i) {
            int idx = i * 512 + tid;
            cp16(As_b + idx * 16, Ag + idx * 8);
        }
        {
            int i = tid;
            int kk = i / 25, cq = (i - kk * 25) * 4;
            cp8(Bs_b + (kk * BSHB + cq) * 2,
                g_uh + (size_t)(kc * 32 + kk) * NCOL + col0 + cq);
            i = tid + 512;
            if (i < 800) {
                kk = i / 25; cq = (i - kk * 25) * 4;
                cp8(Bs_b + (kk * BSHB + cq) * 2,
                    g_uh + (size_t)(kc * 32 + kk) * NCOL + col0 + cq);
            }
        }
        asm volatile("cp.async.commit_group;" ::: "memory");
    };

    load_chunk(0, 0);
    load_chunk(1, 1);
    load_chunk(2, 2);
    load_chunk(3, 3);

    const int matid = lane >> 3;
    const int mrow = lane & 7;
    const int lds_row = (matid & 1) * 8 + mrow;
    const int lds_fn0 = wn * 7 + (matid >> 1);

    for (int it = 0; it < NKC / 2; ++it) {
        if (it < NKC / 2 - 1) asm volatile("cp.async.wait_group 2;" ::: "memory");
        else                  asm volatile("cp.async.wait_group 0;" ::: "memory");
        __syncthreads();

#pragma unroll
        for (int h = 0; h < 2; ++h) {
            const int kc = 2 * it + h;
            const int s = kc & 3;
            const __half* As = sh + (size_t)s * STAGE_B / 2;
            const uint32_t Bs_b = smem_base + (uint32_t)s * STAGE_B + ASTG * 2;

#pragma unroll
            for (int k16 = 0; k16 < 2; ++k16) {
                uint4 a0 = *(const uint4*)(As + (((wm * 2 + k16) * 2 + 0) << 8) + lane * 8);
                uint4 a1 = *(const uint4*)(As + (((wm * 2 + k16) * 2 + 1) << 8) + lane * 8);
                uint32_t bfr[16];
                uint32_t baddr = Bs_b + ((k16 * 16 + lds_row) * BSHB + lds_fn0 * 8) * 2;
#pragma unroll
                for (int j = 0; j < 4; ++j) {
                    if (wn == 0 || j < 3)
                        LDSM_X4_T(bfr[4 * j], bfr[4 * j + 1], bfr[4 * j + 2], bfr[4 * j + 3],
                                  baddr + j * 32);
                }
#pragma unroll
                for (int f = 0; f < 7; ++f) {
                    if (f < fnc) {
                        mma_f16(acc[0][f], a0.x, a0.y, a0.z, a0.w, bfr[2 * f], bfr[2 * f + 1]);
                        mma_f16(acc[1][f], a1.x, a1.y, a1.z, a1.w, bfr[2 * f], bfr[2 * f + 1]);
                    }
                }
            }
        }
        __syncthreads();
        if (2 * it + 5 < NKC) {
            load_chunk((2 * it + 4) & 3, 2 * it + 4);
            load_chunk((2 * it + 5) & 3, 2 * it + 5);
        }
    }
    __syncthreads();

    // ---------- epilogue: stage z + bias into Cs[e][c] ----------
    float* Cs = dyns;
#pragma unroll
    for (int fm = 0; fm < 2; ++fm)
#pragma unroll
        for (int f = 0; f < 7; ++f)
#pragma unroll
            for (int r = 0; r < 4; ++r) {
                int nn = wn * 56 + f * 8 + 2 * tig + (r & 1);
                if (f < fnc && nn < BN) {
                    int c = wm * 32 + fm * 16 + grp + ((r & 2) ? 8 : 0);
                    int g = nn / 25;
                    int w = nn - g * 25;
                    int mf = mf0 + g;
                    float cnt = (float)((mf + 1 < 9) ? (mf + 1) : 9);
                    Cs[nn * CS_STRIDE + c] = acc[fm][f][r] + cnt * g_bias2[c * VV + w];
                }
            }
    __syncthreads();

    // ---------- LN stats ----------
    {
        const int half = tid >> 8;
        const int c = tid & 255;
        float s0 = 0.f, q0 = 0.f, s1 = 0.f, q1 = 0.f;
        const float* c0p = Cs + (half * 2 + 0) * 25 * CS_STRIDE + c;
        const float* c1p = Cs + (half * 2 + 1) * 25 * CS_STRIDE + c;
#pragma unroll
        for (int w = 0; w < 25; ++w) {
            float v0 = c0p[w * CS_STRIDE];
            float v1 = c1p[w * CS_STRIDE];
            s0 += v0; q0 += v0 * v0;
            s1 += v1; q1 += v1 * v1;
        }
#pragma unroll
        for (int off = 16; off > 0; off >>= 1) {
            s0 += __shfl_down_sync(0xffffffffu, s0, off);
            q0 += __shfl_down_sync(0xffffffffu, q0, off);
            s1 += __shfl_down_sync(0xffffffffu, s1, off);
            q1 += __shfl_down_sync(0xffffffffu, q1, off);
        }
        if (lane == 0) {
            red[warp][0] = s0; red[warp][1] = q0;
            red[warp][2] = s1; red[warp][3] = q1;
        }
    }
    __syncthreads();
    if (tid < 4) {
        int hw = (tid >> 1) * 8;
        int sel = (tid & 1) * 2;
        float s = 0.f, q = 0.f;
#pragma unroll
        for (int w = 0; w < 8; ++w) { s += red[hw + w][sel]; q += red[hw + w][sel + 1]; }
        const float inv = 1.f / 6400.f;
        float mean = s * inv;
        float var = q * inv - mean * mean;
        smean[tid] = mean;
        srstd[tid] = rsqrtf(var + 1e-5f);
    }
    __syncthreads();

    // ---------- apply LN + gamma/beta + relu in Cs ----------
    {
        const int half = tid >> 8;
        const int c = tid & 255;
        const float* gm = gamma + c * VV;
        const float* bt = beta + c * VV;
#pragma unroll
        for (int gg = 0; gg < 2; ++gg) {
            int g = half * 2 + gg;
            float mean = smean[g], rstd = srstd[g];
            float* cp = Cs + g * 25 * CS_STRIDE + c;
            for (int w = 0; w < 25; ++w) {
                float z = cp[w * CS_STRIDE];
                float yv = (z - mean) * rstd * gm[w] + bt[w];
                cp[w * CS_STRIDE] = fmaxf(yv, 0.f);
            }
        }
    }
    __syncthreads();

    // ---------- residual + final relu, coalesced float4 ----------
    for (int i = 0; i < 13; ++i) {
        int idx = i * 512 + tid;
        if (idx < 6400) {
            int c = idx / 25;
            int j = idx - c * 25;
            size_t base = ((size_t)(n * CIN + c)) * CPN + loc0 + j * 4;
            float4 xv = *(const float4*)(x + base);
            int e = j * 4;
            float4 yv;
            yv.x = fmaxf(Cs[(e + 0) * CS_STRIDE + c] + xv.x, 0.f);
            yv.y = fmaxf(Cs[(e + 1) * CS_STRIDE + c] + xv.y, 0.f);
            yv.z = fmaxf(Cs[(e + 2) * CS_STRIDE + c] + xv.z, 0.f);
            yv.w = fmaxf(Cs[(e + 3) * CS_STRIDE + c] + xv.w, 0.f);
            *(float4*)(out + base) = yv;
        }
    }
}

// ---------------------------------------------------------------------------
extern "C" void kernel_launch(void* const* d_in, const int* in_sizes, int n_in,
                              void* d_out, int out_size) {
    const float* x      = (const float*)d_in[0];
    const float* A      = (const float*)d_in[1];
    const float* conv_w = (const float*)d_in[2];
    const float* conv_b = (const float*)d_in[3];
    const float* gamma  = (const float*)d_in[4];
    const float* beta   = (const float*)d_in[5];
    const float* ei     = (const float*)d_in[6];
    float* out = (float*)d_out;

    cudaFuncSetAttribute(gemm_kernel, cudaFuncAttributeMaxDynamicSharedMemorySize, GEMM_SMEM);
    cudaFuncSetAttribute(u_kernel, cudaFuncAttributeMaxDynamicSharedMemorySize, U2_SMEM);

    prep_kernel<<<(COUT * KDIM + 255) / 256, 256>>>(A, conv_w, conv_b, ei);

    dim3 gu(CIN, NB);
    u_kernel<<<gu, 256, U2_SMEM>>>(x);

    gemm_kernel<<<NCOL / BN, 512, GEMM_SMEM>>>(x, gamma, beta, out);
}